// round 1
// baseline (speedup 1.0000x reference)
#include <cuda_runtime.h>
#include <math.h>

#define N_NODES 100000
#define D 128

// Scratch (no allocations allowed): degrees [set][0=out(src)/1=in(dst)][node], agg [set][node*128]
__device__ float g_deg[2][2][N_NODES];
__device__ float g_agg[2][(size_t)N_NODES * D];

// ---------------- zero scratch ----------------
__global__ void zero_kernel() {
    size_t stride = (size_t)gridDim.x * blockDim.x;
    size_t tid = (size_t)blockIdx.x * blockDim.x + threadIdx.x;

    float* deg = &g_deg[0][0][0];
    size_t ndeg = 2ull * 2ull * N_NODES;
    for (size_t i = tid; i < ndeg; i += stride) deg[i] = 0.0f;

    float4* agg = reinterpret_cast<float4*>(&g_agg[0][0]);
    size_t nagg4 = 2ull * N_NODES * (D / 4);
    float4 z = make_float4(0.f, 0.f, 0.f, 0.f);
    for (size_t i = tid; i < nagg4; i += stride) agg[i] = z;
}

// ---------------- degree histograms (both sets) ----------------
__global__ void degree_kernel(const int* __restrict__ sp, const int* __restrict__ dp,
                              const int* __restrict__ sn, const int* __restrict__ dn, int E) {
    int i = blockIdx.x * blockDim.x + threadIdx.x;
    if (i >= E) return;
    atomicAdd(&g_deg[0][0][sp[i]], 1.0f);
    atomicAdd(&g_deg[0][1][dp[i]], 1.0f);
    atomicAdd(&g_deg[1][0][sn[i]], 1.0f);
    atomicAdd(&g_deg[1][1][dn[i]], 1.0f);
}

// ---------------- edge scatter: agg[dst] += feats[src] * norm_s[src] ----------------
// One warp per edge; each lane handles 4 consecutive floats (32*4 = 128).
__global__ void scatter_kernel(const float* __restrict__ feats,
                               const int* __restrict__ src, const int* __restrict__ dst,
                               int E, int set) {
    int w = (blockIdx.x * blockDim.x + threadIdx.x) >> 5;
    int lane = threadIdx.x & 31;
    if (w >= E) return;

    int s = src[w];
    int d = dst[w];
    float deg = g_deg[set][0][s];
    float ns = (deg > 0.0f) ? rsqrtf(deg) : 0.0f;

    float4 v = reinterpret_cast<const float4*>(feats)[(size_t)s * (D / 4) + lane];
    v.x *= ns; v.y *= ns; v.z *= ns; v.w *= ns;

    float* a = &g_agg[set][(size_t)d * D + lane * 4];
    asm volatile("red.global.add.v4.f32 [%0], {%1, %2, %3, %4};"
                 :: "l"(a), "f"(v.x), "f"(v.y), "f"(v.z), "f"(v.w) : "memory");
}

// ---------------- fused norm_d * GEMM + bias + PReLU ----------------
// Block: 128 rows x full 128 cols. 256 threads, each computes 8x8.
// Dynamic smem: Ws[128*128] + As[128*128] + norms[128]
__global__ void gemm_kernel(const float* __restrict__ W, const float* __restrict__ b,
                            const float* __restrict__ prelu_a, float* __restrict__ out) {
    extern __shared__ float sm[];
    float* Ws = sm;                 // [k][n] row-major, 128x128
    float* As = sm + D * D;         // [row][k], 128x128
    float* norms = sm + 2 * D * D;  // [128]

    int set = blockIdx.y;
    const float* agg = &g_agg[set][0];
    float* out_set = out + (size_t)set * N_NODES * D;

    int tid = threadIdx.x;
    int row0 = blockIdx.x * D;

    // load W (16K floats, 4K float4): 256 threads x 16 float4
    {
        const float4* Wv = reinterpret_cast<const float4*>(W);
        float4* Wsv = reinterpret_cast<float4*>(Ws);
        #pragma unroll
        for (int i = tid; i < D * D / 4; i += 256) Wsv[i] = Wv[i];
    }
    // per-row norm_d
    if (tid < D) {
        int grow = row0 + tid;
        float nd = 0.0f;
        if (grow < N_NODES) {
            float deg = g_deg[set][1][grow];
            nd = (deg > 0.0f) ? rsqrtf(deg) : 0.0f;
        }
        norms[tid] = nd;
    }
    __syncthreads();

    // load A tile with norm applied: 128 rows x 32 float4
    {
        const float4* Av = reinterpret_cast<const float4*>(agg);
        float4* Asv = reinterpret_cast<float4*>(As);
        #pragma unroll
        for (int idx = tid; idx < D * (D / 4); idx += 256) {
            int row = idx >> 5;          // /32
            int c4  = idx & 31;
            int grow = row0 + row;
            float4 v = make_float4(0.f, 0.f, 0.f, 0.f);
            if (grow < N_NODES) {
                v = Av[(size_t)grow * (D / 4) + c4];
                float nd = norms[row];
                v.x *= nd; v.y *= nd; v.z *= nd; v.w *= nd;
            }
            Asv[row * (D / 4) + c4] = v;
        }
    }
    __syncthreads();

    int ty = tid >> 4;   // 0..15 -> rows ty*8..ty*8+7
    int tx = tid & 15;   // 0..15 -> cols tx*8..tx*8+7

    float acc[8][8];
    #pragma unroll
    for (int i = 0; i < 8; i++)
        #pragma unroll
        for (int j = 0; j < 8; j++) acc[i][j] = 0.0f;

    #pragma unroll 4
    for (int k = 0; k < D; k++) {
        float a[8];
        #pragma unroll
        for (int i = 0; i < 8; i++) a[i] = As[(ty * 8 + i) * D + k];
        float4 b0 = *reinterpret_cast<const float4*>(&Ws[k * D + tx * 8]);
        float4 b1 = *reinterpret_cast<const float4*>(&Ws[k * D + tx * 8 + 4]);
        float bb[8] = {b0.x, b0.y, b0.z, b0.w, b1.x, b1.y, b1.z, b1.w};
        #pragma unroll
        for (int i = 0; i < 8; i++)
            #pragma unroll
            for (int j = 0; j < 8; j++)
                acc[i][j] = fmaf(a[i], bb[j], acc[i][j]);
    }

    float pa = prelu_a[0];
    float4 bv0 = *reinterpret_cast<const float4*>(&b[tx * 8]);
    float4 bv1 = *reinterpret_cast<const float4*>(&b[tx * 8 + 4]);
    float bias[8] = {bv0.x, bv0.y, bv0.z, bv0.w, bv1.x, bv1.y, bv1.z, bv1.w};

    #pragma unroll
    for (int i = 0; i < 8; i++) {
        int grow = row0 + ty * 8 + i;
        if (grow >= N_NODES) continue;
        float res[8];
        #pragma unroll
        for (int j = 0; j < 8; j++) {
            float h = acc[i][j] + bias[j];
            res[j] = (h > 0.0f) ? h : pa * h;
        }
        float4* o = reinterpret_cast<float4*>(&out_set[(size_t)grow * D + tx * 8]);
        o[0] = make_float4(res[0], res[1], res[2], res[3]);
        o[1] = make_float4(res[4], res[5], res[6], res[7]);
    }
}

extern "C" void kernel_launch(void* const* d_in, const int* in_sizes, int n_in,
                              void* d_out, int out_size) {
    const float* feats   = (const float*)d_in[0];
    const float* W       = (const float*)d_in[1];
    const float* b       = (const float*)d_in[2];
    const float* prelu_a = (const float*)d_in[3];
    const int* src_pos   = (const int*)d_in[4];
    const int* dst_pos   = (const int*)d_in[5];
    const int* src_neg   = (const int*)d_in[6];
    const int* dst_neg   = (const int*)d_in[7];
    int E = in_sizes[4];
    float* out = (float*)d_out;

    zero_kernel<<<2048, 256>>>();
    degree_kernel<<<(E + 255) / 256, 256>>>(src_pos, dst_pos, src_neg, dst_neg, E);

    // one warp per edge; run sets sequentially to keep (feats + agg_set) L2-resident
    int sblocks = (E + 7) / 8;  // 8 warps per 256-thread block
    scatter_kernel<<<sblocks, 256>>>(feats, src_pos, dst_pos, E, 0);
    scatter_kernel<<<sblocks, 256>>>(feats, src_neg, dst_neg, E, 1);

    int smem = (2 * D * D + D) * sizeof(float);
    cudaFuncSetAttribute(gemm_kernel, cudaFuncAttributeMaxDynamicSharedMemorySize, smem);
    dim3 grid((N_NODES + D - 1) / D, 2);
    gemm_kernel<<<grid, 256, smem>>>(W, b, prelu_a, out);
}

// round 3
// speedup vs baseline: 1.3644x; 1.3644x over previous
#include <cuda_runtime.h>
#include <math.h>

#define N_NODES 100000
#define D 128

// Scratch: degrees [set][0=out(src)/1=in(dst)][node], Y = feats @ W  [N,128]
__device__ float g_deg[2][2][N_NODES];
__device__ float g_y[(size_t)N_NODES * D];

// ---------------- degree histograms (both sets) ----------------
__global__ void degree_kernel(const int* __restrict__ sp, const int* __restrict__ dp,
                              const int* __restrict__ sn, const int* __restrict__ dn, int E) {
    int i = blockIdx.x * blockDim.x + threadIdx.x;
    if (i >= E) return;
    atomicAdd(&g_deg[0][0][sp[i]], 1.0f);
    atomicAdd(&g_deg[0][1][dp[i]], 1.0f);
    atomicAdd(&g_deg[1][0][sn[i]], 1.0f);
    atomicAdd(&g_deg[1][1][dn[i]], 1.0f);
}

// ---------------- Y = feats @ W  (128x128 fp32 GEMM, 128-row tiles) ----------------
// Block: 128 rows. 256 threads, each computes 8x8. smem: Ws[128*128] + As[128*128]
__global__ void ygemm_kernel(const float* __restrict__ feats, const float* __restrict__ W) {
    extern __shared__ float sm[];
    float* Ws = sm;            // [k][n]
    float* As = sm + D * D;    // [row][k]

    int tid = threadIdx.x;
    int row0 = blockIdx.x * D;

    {
        const float4* Wv = reinterpret_cast<const float4*>(W);
        float4* Wsv = reinterpret_cast<float4*>(Ws);
        #pragma unroll
        for (int i = tid; i < D * D / 4; i += 256) Wsv[i] = Wv[i];
    }
    {
        const float4* Av = reinterpret_cast<const float4*>(feats);
        float4* Asv = reinterpret_cast<float4*>(As);
        #pragma unroll
        for (int idx = tid; idx < D * (D / 4); idx += 256) {
            int row = idx >> 5;
            int c4  = idx & 31;
            int grow = row0 + row;
            float4 v = make_float4(0.f, 0.f, 0.f, 0.f);
            if (grow < N_NODES) v = Av[(size_t)grow * (D / 4) + c4];
            Asv[idx] = v;
        }
    }
    __syncthreads();

    int ty = tid >> 4;
    int tx = tid & 15;

    float acc[8][8];
    #pragma unroll
    for (int i = 0; i < 8; i++)
        #pragma unroll
        for (int j = 0; j < 8; j++) acc[i][j] = 0.0f;

    #pragma unroll 4
    for (int k = 0; k < D; k++) {
        float a[8];
        #pragma unroll
        for (int i = 0; i < 8; i++) a[i] = As[(ty * 8 + i) * D + k];
        float4 b0 = *reinterpret_cast<const float4*>(&Ws[k * D + tx * 8]);
        float4 b1 = *reinterpret_cast<const float4*>(&Ws[k * D + tx * 8 + 4]);
        float bb[8] = {b0.x, b0.y, b0.z, b0.w, b1.x, b1.y, b1.z, b1.w};
        #pragma unroll
        for (int i = 0; i < 8; i++)
            #pragma unroll
            for (int j = 0; j < 8; j++)
                acc[i][j] = fmaf(a[i], bb[j], acc[i][j]);
    }

    #pragma unroll
    for (int i = 0; i < 8; i++) {
        int grow = row0 + ty * 8 + i;
        if (grow >= N_NODES) continue;
        float4* o = reinterpret_cast<float4*>(&g_y[(size_t)grow * D + tx * 8]);
        o[0] = make_float4(acc[i][0], acc[i][1], acc[i][2], acc[i][3]);
        o[1] = make_float4(acc[i][4], acc[i][5], acc[i][6], acc[i][7]);
    }
}

// ---------------- edge scatter: out[dst] += Y[src] * norm_s[src] ----------------
// One warp per 2 edges (independent chains for MLP); lane handles 4 floats.
// deg indexed via g_deg[set][0] in DEVICE code (host-side &g_deg is invalid!)
__global__ void scatter_kernel(const int* __restrict__ src, const int* __restrict__ dst,
                               int E, float* __restrict__ outset, int set) {
    int w = (blockIdx.x * blockDim.x + threadIdx.x) >> 5;
    int lane = threadIdx.x & 31;
    int e0 = w * 2;
    if (e0 >= E) return;

    const float* deg_out = &g_deg[set][0][0];
    const float4* Yv = reinterpret_cast<const float4*>(&g_y[0]);

    int s0 = src[e0], d0 = dst[e0];
    bool has1 = (e0 + 1) < E;
    int s1 = has1 ? src[e0 + 1] : s0;
    int d1 = has1 ? dst[e0 + 1] : d0;

    float dg0 = deg_out[s0];
    float dg1 = deg_out[s1];
    float4 v0 = Yv[(size_t)s0 * (D / 4) + lane];
    float4 v1 = Yv[(size_t)s1 * (D / 4) + lane];

    float ns0 = (dg0 > 0.0f) ? rsqrtf(dg0) : 0.0f;
    float ns1 = (dg1 > 0.0f) ? rsqrtf(dg1) : 0.0f;

    v0.x *= ns0; v0.y *= ns0; v0.z *= ns0; v0.w *= ns0;
    float* a0 = &outset[(size_t)d0 * D + lane * 4];
    asm volatile("red.global.add.v4.f32 [%0], {%1, %2, %3, %4};"
                 :: "l"(a0), "f"(v0.x), "f"(v0.y), "f"(v0.z), "f"(v0.w) : "memory");

    if (has1) {
        v1.x *= ns1; v1.y *= ns1; v1.z *= ns1; v1.w *= ns1;
        float* a1 = &outset[(size_t)d1 * D + lane * 4];
        asm volatile("red.global.add.v4.f32 [%0], {%1, %2, %3, %4};"
                     :: "l"(a1), "f"(v1.x), "f"(v1.y), "f"(v1.z), "f"(v1.w) : "memory");
    }
}

// ---------------- epilogue: out = prelu(out * norm_d[row] + b) in-place ----------------
__global__ void epilogue_kernel(float* __restrict__ out, const float* __restrict__ b,
                                const float* __restrict__ prelu_a) {
    size_t idx = (size_t)blockIdx.x * blockDim.x + threadIdx.x;  // float4 index
    size_t total = 2ull * N_NODES * (D / 4);
    if (idx >= total) return;

    size_t per_set = (size_t)N_NODES * (D / 4);
    int set = (int)(idx / per_set);
    size_t rem = idx - (size_t)set * per_set;
    int row = (int)(rem >> 5);
    int c4 = (int)(rem & 31);

    float deg = g_deg[set][1][row];
    float nd = (deg > 0.0f) ? rsqrtf(deg) : 0.0f;
    float pa = prelu_a[0];

    float4 v = reinterpret_cast<float4*>(out)[idx];
    float4 bb = reinterpret_cast<const float4*>(b)[c4];

    float h0 = v.x * nd + bb.x;
    float h1 = v.y * nd + bb.y;
    float h2 = v.z * nd + bb.z;
    float h3 = v.w * nd + bb.w;
    v.x = (h0 > 0.f) ? h0 : pa * h0;
    v.y = (h1 > 0.f) ? h1 : pa * h1;
    v.z = (h2 > 0.f) ? h2 : pa * h2;
    v.w = (h3 > 0.f) ? h3 : pa * h3;
    reinterpret_cast<float4*>(out)[idx] = v;
}

extern "C" void kernel_launch(void* const* d_in, const int* in_sizes, int n_in,
                              void* d_out, int out_size) {
    const float* feats   = (const float*)d_in[0];
    const float* W       = (const float*)d_in[1];
    const float* b       = (const float*)d_in[2];
    const float* prelu_a = (const float*)d_in[3];
    const int* src_pos   = (const int*)d_in[4];
    const int* dst_pos   = (const int*)d_in[5];
    const int* src_neg   = (const int*)d_in[6];
    const int* dst_neg   = (const int*)d_in[7];
    int E = in_sizes[4];
    float* out = (float*)d_out;

    // zero deg + out (graph-capturable async memsets)
    void* deg_ptr = nullptr;
    cudaGetSymbolAddress(&deg_ptr, g_deg);
    cudaMemsetAsync(deg_ptr, 0, sizeof(float) * 2 * 2 * N_NODES);
    cudaMemsetAsync(out, 0, sizeof(float) * 2ull * N_NODES * D);

    degree_kernel<<<(E + 255) / 256, 256>>>(src_pos, dst_pos, src_neg, dst_neg, E);

    int smem = 2 * D * D * sizeof(float);
    cudaFuncSetAttribute(ygemm_kernel, cudaFuncAttributeMaxDynamicSharedMemorySize, smem);
    ygemm_kernel<<<(N_NODES + D - 1) / D, 256, smem>>>(feats, W);

    // one warp per 2 edges; 8 warps per 256-thread block
    int warps = (E + 1) / 2;
    int sblocks = (warps + 7) / 8;
    float* out_pos = out;
    float* out_neg = out + (size_t)N_NODES * D;
    scatter_kernel<<<sblocks, 256>>>(src_pos, dst_pos, E, out_pos, 0);
    scatter_kernel<<<sblocks, 256>>>(src_neg, dst_neg, E, out_neg, 1);

    size_t etotal = 2ull * N_NODES * (D / 4);
    epilogue_kernel<<<(int)((etotal + 255) / 256), 256>>>(out, b, prelu_a);
}

// round 4
// speedup vs baseline: 1.4152x; 1.0372x over previous
#include <cuda_runtime.h>
#include <math.h>

#define N_NODES 100000
#define D 128

// Scratch: degrees [set][0=out(src)/1=in(dst)][node], Y = feats @ W  [N,128]
__device__ float g_deg[2][2][N_NODES];
__device__ float g_y[(size_t)N_NODES * D];

// ---------------- degree histograms (both sets) ----------------
__global__ void degree_kernel(const int* __restrict__ sp, const int* __restrict__ dp,
                              const int* __restrict__ sn, const int* __restrict__ dn, int E) {
    int i = blockIdx.x * blockDim.x + threadIdx.x;
    if (i >= E) return;
    atomicAdd(&g_deg[0][0][sp[i]], 1.0f);
    atomicAdd(&g_deg[0][1][dp[i]], 1.0f);
    atomicAdd(&g_deg[1][0][sn[i]], 1.0f);
    atomicAdd(&g_deg[1][1][dn[i]], 1.0f);
}

// ---------------- Y = feats @ W  (128x128 fp32 GEMM, 128-row tiles) ----------------
__global__ void ygemm_kernel(const float* __restrict__ feats, const float* __restrict__ W) {
    extern __shared__ float sm[];
    float* Ws = sm;            // [k][n]
    float* As = sm + D * D;    // [row][k]

    int tid = threadIdx.x;
    int row0 = blockIdx.x * D;

    {
        const float4* Wv = reinterpret_cast<const float4*>(W);
        float4* Wsv = reinterpret_cast<float4*>(Ws);
        #pragma unroll
        for (int i = tid; i < D * D / 4; i += 256) Wsv[i] = Wv[i];
    }
    {
        const float4* Av = reinterpret_cast<const float4*>(feats);
        float4* Asv = reinterpret_cast<float4*>(As);
        #pragma unroll
        for (int idx = tid; idx < D * (D / 4); idx += 256) {
            int row = idx >> 5;
            int c4  = idx & 31;
            int grow = row0 + row;
            float4 v = make_float4(0.f, 0.f, 0.f, 0.f);
            if (grow < N_NODES) v = Av[(size_t)grow * (D / 4) + c4];
            Asv[idx] = v;
        }
    }
    __syncthreads();

    int ty = tid >> 4;
    int tx = tid & 15;

    float acc[8][8];
    #pragma unroll
    for (int i = 0; i < 8; i++)
        #pragma unroll
        for (int j = 0; j < 8; j++) acc[i][j] = 0.0f;

    #pragma unroll 4
    for (int k = 0; k < D; k++) {
        float a[8];
        #pragma unroll
        for (int i = 0; i < 8; i++) a[i] = As[(ty * 8 + i) * D + k];
        float4 b0 = *reinterpret_cast<const float4*>(&Ws[k * D + tx * 8]);
        float4 b1 = *reinterpret_cast<const float4*>(&Ws[k * D + tx * 8 + 4]);
        float bb[8] = {b0.x, b0.y, b0.z, b0.w, b1.x, b1.y, b1.z, b1.w};
        #pragma unroll
        for (int i = 0; i < 8; i++)
            #pragma unroll
            for (int j = 0; j < 8; j++)
                acc[i][j] = fmaf(a[i], bb[j], acc[i][j]);
    }

    #pragma unroll
    for (int i = 0; i < 8; i++) {
        int grow = row0 + ty * 8 + i;
        if (grow >= N_NODES) continue;
        float4* o = reinterpret_cast<float4*>(&g_y[(size_t)grow * D + tx * 8]);
        o[0] = make_float4(acc[i][0], acc[i][1], acc[i][2], acc[i][3]);
        o[1] = make_float4(acc[i][4], acc[i][5], acc[i][6], acc[i][7]);
    }
}

// ---------------- edge scatter: out[dst] += Y[src] * ns[src] * nd[dst] ----------------
// 4 edges per warp; all gathers issued before any RED (MLP depth 4).
__global__ void scatter_kernel(const int* __restrict__ src, const int* __restrict__ dst,
                               int E, float* __restrict__ outset, int set) {
    int w = (blockIdx.x * blockDim.x + threadIdx.x) >> 5;
    int lane = threadIdx.x & 31;
    int e0 = w * 4;
    if (e0 >= E) return;
    int n = E - e0; if (n > 4) n = 4;

    const float4* Yv = reinterpret_cast<const float4*>(&g_y[0]);

    int s[4], d[4];
    #pragma unroll
    for (int i = 0; i < 4; i++) {
        int e = e0 + ((i < n) ? i : 0);
        s[i] = src[e];
        d[i] = dst[e];
    }

    // degree loads (warp-broadcast), independent chains
    float dgs[4], dgd[4];
    #pragma unroll
    for (int i = 0; i < 4; i++) {
        dgs[i] = g_deg[set][0][s[i]];
        dgd[i] = g_deg[set][1][d[i]];
    }

    // Y gathers: 4 independent 128B vector loads in flight
    float4 v[4];
    #pragma unroll
    for (int i = 0; i < 4; i++) v[i] = Yv[(size_t)s[i] * (D / 4) + lane];

    float c[4];
    #pragma unroll
    for (int i = 0; i < 4; i++) {
        float ns = (dgs[i] > 0.0f) ? rsqrtf(dgs[i]) : 0.0f;
        float nd = (dgd[i] > 0.0f) ? rsqrtf(dgd[i]) : 0.0f;
        c[i] = ns * nd;
    }

    #pragma unroll
    for (int i = 0; i < 4; i++) {
        if (i >= n) break;
        float4 t = v[i];
        t.x *= c[i]; t.y *= c[i]; t.z *= c[i]; t.w *= c[i];
        float* a = &outset[(size_t)d[i] * D + lane * 4];
        asm volatile("red.global.add.v4.f32 [%0], {%1, %2, %3, %4};"
                     :: "l"(a), "f"(t.x), "f"(t.y), "f"(t.z), "f"(t.w) : "memory");
    }
}

// ---------------- epilogue: out = prelu(out + b) in-place (norms already folded) ----------------
__global__ void epilogue_kernel(float* __restrict__ out, const float* __restrict__ b,
                                const float* __restrict__ prelu_a) {
    size_t idx = (size_t)blockIdx.x * blockDim.x + threadIdx.x;  // float4 index
    size_t total = 2ull * N_NODES * (D / 4);
    if (idx >= total) return;

    int c4 = (int)(idx & 31);
    float pa = prelu_a[0];

    float4 v = reinterpret_cast<float4*>(out)[idx];
    float4 bb = reinterpret_cast<const float4*>(b)[c4];

    float h0 = v.x + bb.x;
    float h1 = v.y + bb.y;
    float h2 = v.z + bb.z;
    float h3 = v.w + bb.w;
    v.x = (h0 > 0.f) ? h0 : pa * h0;
    v.y = (h1 > 0.f) ? h1 : pa * h1;
    v.z = (h2 > 0.f) ? h2 : pa * h2;
    v.w = (h3 > 0.f) ? h3 : pa * h3;
    reinterpret_cast<float4*>(out)[idx] = v;
}

extern "C" void kernel_launch(void* const* d_in, const int* in_sizes, int n_in,
                              void* d_out, int out_size) {
    const float* feats   = (const float*)d_in[0];
    const float* W       = (const float*)d_in[1];
    const float* b       = (const float*)d_in[2];
    const float* prelu_a = (const float*)d_in[3];
    const int* src_pos   = (const int*)d_in[4];
    const int* dst_pos   = (const int*)d_in[5];
    const int* src_neg   = (const int*)d_in[6];
    const int* dst_neg   = (const int*)d_in[7];
    int E = in_sizes[4];
    float* out = (float*)d_out;

    void* deg_ptr = nullptr;
    cudaGetSymbolAddress(&deg_ptr, g_deg);
    cudaMemsetAsync(deg_ptr, 0, sizeof(float) * 2 * 2 * N_NODES);
    cudaMemsetAsync(out, 0, sizeof(float) * 2ull * N_NODES * D);

    degree_kernel<<<(E + 255) / 256, 256>>>(src_pos, dst_pos, src_neg, dst_neg, E);

    int smem = 2 * D * D * sizeof(float);
    cudaFuncSetAttribute(ygemm_kernel, cudaFuncAttributeMaxDynamicSharedMemorySize, smem);
    ygemm_kernel<<<(N_NODES + D - 1) / D, 256, smem>>>(feats, W);

    // one warp per 4 edges; 8 warps per 256-thread block
    int warps = (E + 3) / 4;
    int sblocks = (warps + 7) / 8;
    float* out_pos = out;
    float* out_neg = out + (size_t)N_NODES * D;
    scatter_kernel<<<sblocks, 256>>>(src_pos, dst_pos, E, out_pos, 0);
    scatter_kernel<<<sblocks, 256>>>(src_neg, dst_neg, E, out_neg, 1);

    size_t etotal = 2ull * N_NODES * (D / 4);
    epilogue_kernel<<<(int)((etotal + 255) / 256), 256>>>(out, b, prelu_a);
}